// round 9
// baseline (speedup 1.0000x reference)
#include <cuda_runtime.h>

#define TPB 128
typedef unsigned long long ull;

// MULT = pi - float-eps, folded into the stage-E quadratic form.
#define MULT_F (3.141592653589793 - 1.1920928955078125e-07)

// Precomputed (theta-dependent, batch-invariant), row-major broadcast layout:
__device__ __align__(16) float2 g_W12[12 * 256];   // unitaries, circuits 0..11 (stages A,B,C)
__device__ __align__(16) float  g_M[5 * 256];      // quadratic forms, circuits 12..16 (D,E)

// theta slice per circuit: A->theta[0], B->theta[3], C->theta[4], D->theta[1], E->theta[2][0]
__device__ __forceinline__ int circ_slice(int c) {
    if (c < 4)  return c;
    if (c < 8)  return 12 + (c - 4);
    if (c < 12) return 16 + (c - 8);
    if (c < 16) return 4 + (c - 12);
    return 8;
}

// One block per circuit (16 threads = 16 basis columns).
__global__ void build_WM(const float* __restrict__ theta) {
    const int c = blockIdx.x, col = threadIdx.x;
    const float* w = theta + circ_slice(c) * 48;

    float sr[16], si[16];
#pragma unroll
    for (int i = 0; i < 16; i++) { sr[i] = (i == col) ? 1.f : 0.f; si[i] = 0.f; }
#pragma unroll
    for (int l = 0; l < 4; l++) {
#pragma unroll
        for (int q = 0; q < 4; q++) {
            const float phi = w[(l * 4 + q) * 3 + 0];
            const float th  = w[(l * 4 + q) * 3 + 1];
            const float om  = w[(l * 4 + q) * 3 + 2];
            float ch, sh, ca, sa, cb, sb;
            __sincosf(0.5f * th, &sh, &ch);
            __sincosf(0.5f * (phi + om), &sa, &ca);
            __sincosf(0.5f * (phi - om), &sb, &cb);
            const float u00r =  ca * ch, u00i = -sa * ch;
            const float u01r = -cb * sh, u01i = -sb * sh;
            const float u10r =  cb * sh, u10i = -sb * sh;
            const float u11r =  ca * ch, u11i =  sa * ch;
            const int mask = 8 >> q;
#pragma unroll
            for (int k = 0; k < 16; k++) {
                if (k & mask) continue;
                const int k1 = k | mask;
                float ar = sr[k],  ai = si[k];
                float br = sr[k1], bi = si[k1];
                sr[k]  = u00r * ar - u00i * ai + u01r * br - u01i * bi;
                si[k]  = u00r * ai + u00i * ar + u01r * bi + u01i * br;
                sr[k1] = u10r * ar - u10i * ai + u11r * br - u11i * bi;
                si[k1] = u10r * ai + u10i * ar + u11r * bi + u11i * br;
            }
        }
        const int r = (l % 3) + 1;
#pragma unroll
        for (int q = 0; q < 4; q++) {
            const int cm = 8 >> q;
            const int tm = 8 >> ((q + r) & 3);
#pragma unroll
            for (int k = 0; k < 16; k++) {
                if ((k & cm) && !(k & tm)) {
                    const int k1 = k | tm;
                    float tr = sr[k], ti = si[k];
                    sr[k] = sr[k1]; si[k] = si[k1];
                    sr[k1] = tr;    si[k1] = ti;
                }
            }
        }
    }

    if (c < 12) {
#pragma unroll
        for (int k = 0; k < 16; k++)
            g_W12[c * 256 + k * 16 + col] = make_float2(sr[k], si[k]);
    } else {
        __shared__ float2 sWt[256];
#pragma unroll
        for (int k = 0; k < 16; k++) sWt[k * 16 + col] = make_float2(sr[k], si[k]);
        __syncthreads();
        const int r = col;
        float m[16];
#pragma unroll
        for (int j = 0; j < 16; j++) m[j] = 0.f;
#pragma unroll
        for (int k = 0; k < 16; k++) {
            const float2 wr = sWt[k * 16 + r];
#pragma unroll
            for (int j = 0; j < 16; j++) {
                const float2 wj = sWt[k * 16 + j];
                const float tt = wr.x * wj.x + wr.y * wj.y;
                m[j] = (k & 8) ? (m[j] - tt) : (m[j] + tt);
            }
        }
        const float scale = (c == 16) ? (float)MULT_F : 1.f;
#pragma unroll
        for (int j = 0; j < 16; j++) g_M[(c - 12) * 256 + r * 16 + j] = m[j] * scale;
    }
}

// ---------------------------------------------------------------------------
// f32x2 packed helpers
// ---------------------------------------------------------------------------
__device__ __forceinline__ ull pk2(float lo, float hi) {
    ull r; asm("mov.b64 %0, {%1, %2};" : "=l"(r) : "f"(lo), "f"(hi)); return r;
}
__device__ __forceinline__ void unpk2(ull v, float& lo, float& hi) {
    asm("mov.b64 {%0, %1}, %2;" : "=f"(lo), "=f"(hi) : "l"(v));
}
__device__ __forceinline__ ull ffma2(ull a, ull b, ull c) {
    ull d; asm("fma.rn.f32x2 %0, %1, %2, %3;" : "=l"(d) : "l"(a), "l"(b), "l"(c)); return d;
}
__device__ __forceinline__ ull fmul2(ull a, ull b) {
    ull d; asm("mul.rn.f32x2 %0, %1, %2;" : "=l"(d) : "l"(a), "l"(b)); return d;
}
__device__ __forceinline__ ull fadd2(ull a, ull b) {
    ull d; asm("add.rn.f32x2 %0, %1, %2;" : "=l"(d) : "l"(a), "l"(b)); return d;
}
__device__ __forceinline__ ull fsub2(ull a, ull b) {
    ull d; asm("sub.rn.f32x2 %0, %1, %2;" : "=l"(d) : "l"(a), "l"(b)); return d;
}

__device__ __forceinline__ void emb2(float a0, float a1, float* u) {
    float s0, c0, s1, c1;
    __sincosf(0.5f * a0, &s0, &c0);
    __sincosf(0.5f * a1, &s1, &c1);
    u[0] = c0 * c1; u[1] = c0 * s1; u[2] = s0 * c1; u[3] = s0 * s1;
}

// Full circuit, 4 expvals. W rows packed (re,im) f32x2; all-packed epilogue:
// p2[k] = (yr^2, yi^2), Walsh tree in f32x2, unpack only the 4 outputs.
__device__ __forceinline__ void run4(const ull* __restrict__ W, const float* a, float* o) {
    float u[4], v[4];
    emb2(a[0], a[1], u); emb2(a[2], a[3], v);
    ull pp[16];
#pragma unroll
    for (int i = 0; i < 4; i++)
#pragma unroll
        for (int j = 0; j < 4; j++) { const float t = u[i] * v[j]; pp[i * 4 + j] = pk2(t, t); }
    ull p2[16];
#pragma unroll 4
    for (int k = 0; k < 16; k++) {
        const ulonglong2* row = (const ulonglong2*)(W + k * 16);
        const ulonglong2 w0 = row[0], w1 = row[1];
        ull ac0 = fmul2(w0.x, pp[0]), ac2 = fmul2(w0.y, pp[1]);
        ull ac1 = fmul2(w1.x, pp[2]), ac3 = fmul2(w1.y, pp[3]);
#pragma unroll
        for (int jj = 2; jj < 8; jj += 2) {
            const ulonglong2 wA = row[jj], wB = row[jj + 1];
            ac0 = ffma2(wA.x, pp[2 * jj],     ac0);
            ac2 = ffma2(wA.y, pp[2 * jj + 1], ac2);
            ac1 = ffma2(wB.x, pp[2 * jj + 2], ac1);
            ac3 = ffma2(wB.y, pp[2 * jj + 3], ac3);
        }
        const ull s = fadd2(fadd2(ac0, ac1), fadd2(ac2, ac3));   // (yr, yi)
        p2[k] = fmul2(s, s);                                     // (yr^2, yi^2)
    }
    // Packed Walsh tree (mapping verified in R2: o0<-k&8, o1<-k&4, o2<-k&2, o3<-k&1)
    ull sA[8], dA[8];
#pragma unroll
    for (int j = 0; j < 8; j++) {
        sA[j] = fadd2(p2[2 * j], p2[2 * j + 1]);
        dA[j] = fsub2(p2[2 * j], p2[2 * j + 1]);
    }
    ull e3a = fadd2(fadd2(dA[0], dA[1]), fadd2(dA[2], dA[3]));
    ull e3b = fadd2(fadd2(dA[4], dA[5]), fadd2(dA[6], dA[7]));
    const ull e3 = fadd2(e3a, e3b);
    ull ss[4], sd[4];
#pragma unroll
    for (int m = 0; m < 4; m++) {
        ss[m] = fadd2(sA[2 * m], sA[2 * m + 1]);
        sd[m] = fsub2(sA[2 * m], sA[2 * m + 1]);
    }
    const ull e2 = fadd2(fadd2(sd[0], sd[1]), fadd2(sd[2], sd[3]));
    const ull t0 = fadd2(ss[0], ss[1]), t1 = fadd2(ss[2], ss[3]);
    const ull e0 = fsub2(t0, t1);
    const ull e1 = fadd2(fsub2(ss[0], ss[1]), fsub2(ss[2], ss[3]));
    float lo, hi;
    unpk2(e0, lo, hi); o[0] = lo + hi;
    unpk2(e1, lo, hi); o[1] = lo + hi;
    unpk2(e2, lo, hi); o[2] = lo + hi;
    unpk2(e3, lo, hi); o[3] = lo + hi;
}

// Single expval via real quadratic form e = psi^T M psi (dual chains).
__device__ __forceinline__ float run1(const float* __restrict__ M, const float* a) {
    float u[4], v[4];
    emb2(a[0], a[1], u); emb2(a[2], a[3], v);
    float psi[16];
#pragma unroll
    for (int i = 0; i < 4; i++)
#pragma unroll
        for (int j = 0; j < 4; j++) psi[i * 4 + j] = u[i] * v[j];
    ull pj[8];
#pragma unroll
    for (int j = 0; j < 8; j++) pj[j] = pk2(psi[2 * j], psi[2 * j + 1]);
    float eacc0 = 0.f, eacc1 = 0.f;
#pragma unroll 4
    for (int k = 0; k < 16; k++) {
        const ulonglong2* row = (const ulonglong2*)(M + k * 16);
        const ulonglong2 m0 = row[0], m1 = row[1], m2 = row[2], m3 = row[3];
        ull a0c = fmul2(m0.x, pj[0]);
        ull a1c = fmul2(m0.y, pj[1]);
        a0c = ffma2(m1.x, pj[2], a0c);
        a1c = ffma2(m1.y, pj[3], a1c);
        a0c = ffma2(m2.x, pj[4], a0c);
        a1c = ffma2(m2.y, pj[5], a1c);
        a0c = ffma2(m3.x, pj[6], a0c);
        a1c = ffma2(m3.y, pj[7], a1c);
        const ull s = fadd2(a0c, a1c);
        float lo, hi; unpk2(s, lo, hi);
        if (k & 1) eacc1 = fmaf(psi[k], lo + hi, eacc1);
        else       eacc0 = fmaf(psi[k], lo + hi, eacc0);
    }
    return eacc0 + eacc1;
}

// ---------------------------------------------------------------------------
// Main kernel: block = 32-element tile, warp w = circuit w of each stage,
// lane = element. All W/M reads are full-warp broadcasts.
// ---------------------------------------------------------------------------
__global__ __launch_bounds__(TPB, 7)
void vqc_warp(const float* __restrict__ x, float* __restrict__ out, int B) {
    __shared__ __align__(16) ull   sW[12 * 256];   // 24 KB
    __shared__ __align__(16) float sM[5 * 256];    // 5 KB
    __shared__ float sH[32][17];                   // 2.1 KB, stride-17 pad

    const int tid = threadIdx.x;
    {
        const float4* s1 = (const float4*)g_W12;
        float4* d1 = (float4*)sW;
        for (int i = tid; i < 12 * 128; i += TPB) d1[i] = s1[i];
        const float4* s2 = (const float4*)g_M;
        float4* d2 = (float4*)sM;
        for (int i = tid; i < 5 * 64; i += TPB) d2[i] = s2[i];
    }

    const int e0 = blockIdx.x * 32;                 // tile base element
    for (int i = tid; i < 32 * 13; i += TPB) {
        const long gi = (long)e0 * 13 + i;
        if (gi < (long)B * 13) {
            const int e = i / 13, j = i - 13 * e;
            sH[e][j] = x[gi];
        }
    }
    __syncthreads();

    const int w = tid >> 5;   // warp = circuit index within stage
    const int e = tid & 31;   // lane  = element within tile
    float a[4], o[4];

    // Stage A angles: H = [0, x0..x12, 0, 0]; circuit w uses H[4w..4w+3]
#pragma unroll
    for (int i = 0; i < 4; i++) {
        const int j = 4 * w + i;
        a[i] = (j >= 1 && j <= 13) ? sH[e][j - 1] : 0.f;
    }
    __syncthreads();

    // Stage A
    run4(sW + w * 256, a, o);
#pragma unroll
    for (int i = 0; i < 4; i++) sH[e][4 * w + i] = o[i];
    __syncthreads();
#pragma unroll
    for (int i = 0; i < 4; i++) a[i] = sH[e][4 * i + w];    // transposed wiring
    __syncthreads();

    // Stage B
    run4(sW + (4 + w) * 256, a, o);
#pragma unroll
    for (int i = 0; i < 4; i++) sH[e][4 * w + i] = o[i];
    __syncthreads();
#pragma unroll
    for (int i = 0; i < 4; i++) a[i] = sH[e][4 * i + w];
    __syncthreads();

    // Stage C
    run4(sW + (8 + w) * 256, a, o);
#pragma unroll
    for (int i = 0; i < 4; i++) sH[e][4 * w + i] = o[i];
    __syncthreads();
#pragma unroll
    for (int i = 0; i < 4; i++) a[i] = sH[e][4 * i + w];
    __syncthreads();

    // Stage D: quadratic form w
    const float h4 = run1(sM + w * 256, a);
    sH[e][w] = h4;
    __syncthreads();

    // Stage E: warp 0 only (MULT baked into sM[4]); warp-uniform branch
    if (w != 0) return;
#pragma unroll
    for (int i = 0; i < 4; i++) a[i] = sH[e][i];
    const float r = run1(sM + 4 * 256, a);
    if (e0 + e < B) out[e0 + e] = r;
}

extern "C" void kernel_launch(void* const* d_in, const int* in_sizes, int n_in,
                              void* d_out, int out_size) {
    const float* x     = (const float*)d_in[0];
    const float* theta = (const float*)d_in[1];
    if (n_in >= 2 && in_sizes[0] < in_sizes[1]) {
        x     = (const float*)d_in[1];
        theta = (const float*)d_in[0];
    }
    float* out = (float*)d_out;
    const int B = out_size;

    build_WM<<<17, 16>>>(theta);
    vqc_warp<<<(B + 31) / 32, TPB>>>(x, out, B);
}

// round 10
// speedup vs baseline: 1.0554x; 1.0554x over previous
#include <cuda_runtime.h>

#define TPB 128
typedef unsigned long long ull;

// MULT = pi - float-eps, folded into the stage-E quadratic form.
#define MULT_F (3.141592653589793 - 1.1920928955078125e-07)

// Precomputed (theta-dependent, batch-invariant):
__device__ __align__(16) float2 g_W12[12 * 256];   // unitaries, circuits 0..11 (stages A,B,C)
__device__ __align__(16) float  g_M[5 * 256];      // quadratic forms, circuits 12..16 (D,E)

// theta slice per circuit: A->theta[0], B->theta[3], C->theta[4], D->theta[1], E->theta[2][0]
__device__ __forceinline__ int circ_slice(int c) {
    if (c < 4)  return c;
    if (c < 8)  return 12 + (c - 4);
    if (c < 12) return 16 + (c - 8);
    if (c < 16) return 4 + (c - 12);
    return 8;
}

// One block per circuit (16 threads = 16 basis columns).
__global__ void build_WM(const float* __restrict__ theta) {
    const int c = blockIdx.x, col = threadIdx.x;
    const float* w = theta + circ_slice(c) * 48;

    float sr[16], si[16];
#pragma unroll
    for (int i = 0; i < 16; i++) { sr[i] = (i == col) ? 1.f : 0.f; si[i] = 0.f; }
#pragma unroll
    for (int l = 0; l < 4; l++) {
#pragma unroll
        for (int q = 0; q < 4; q++) {
            const float phi = w[(l * 4 + q) * 3 + 0];
            const float th  = w[(l * 4 + q) * 3 + 1];
            const float om  = w[(l * 4 + q) * 3 + 2];
            float ch, sh, ca, sa, cb, sb;
            __sincosf(0.5f * th, &sh, &ch);
            __sincosf(0.5f * (phi + om), &sa, &ca);
            __sincosf(0.5f * (phi - om), &sb, &cb);
            const float u00r =  ca * ch, u00i = -sa * ch;
            const float u01r = -cb * sh, u01i = -sb * sh;
            const float u10r =  cb * sh, u10i = -sb * sh;
            const float u11r =  ca * ch, u11i =  sa * ch;
            const int mask = 8 >> q;
#pragma unroll
            for (int k = 0; k < 16; k++) {
                if (k & mask) continue;
                const int k1 = k | mask;
                float ar = sr[k],  ai = si[k];
                float br = sr[k1], bi = si[k1];
                sr[k]  = u00r * ar - u00i * ai + u01r * br - u01i * bi;
                si[k]  = u00r * ai + u00i * ar + u01r * bi + u01i * br;
                sr[k1] = u10r * ar - u10i * ai + u11r * br - u11i * bi;
                si[k1] = u10r * ai + u10i * ar + u11r * bi + u11i * br;
            }
        }
        const int r = (l % 3) + 1;
#pragma unroll
        for (int q = 0; q < 4; q++) {
            const int cm = 8 >> q;
            const int tm = 8 >> ((q + r) & 3);
#pragma unroll
            for (int k = 0; k < 16; k++) {
                if ((k & cm) && !(k & tm)) {
                    const int k1 = k | tm;
                    float tr = sr[k], ti = si[k];
                    sr[k] = sr[k1]; si[k] = si[k1];
                    sr[k1] = tr;    si[k1] = ti;
                }
            }
        }
    }

    if (c < 12) {
#pragma unroll
        for (int k = 0; k < 16; k++)
            g_W12[c * 256 + k * 16 + col] = make_float2(sr[k], si[k]);
    } else {
        __shared__ float2 sWt[256];
#pragma unroll
        for (int k = 0; k < 16; k++) sWt[k * 16 + col] = make_float2(sr[k], si[k]);
        __syncthreads();
        const int r = col;
        float m[16];
#pragma unroll
        for (int j = 0; j < 16; j++) m[j] = 0.f;
#pragma unroll
        for (int k = 0; k < 16; k++) {
            const float2 wr = sWt[k * 16 + r];
#pragma unroll
            for (int j = 0; j < 16; j++) {
                const float2 wj = sWt[k * 16 + j];
                const float tt = wr.x * wj.x + wr.y * wj.y;
                m[j] = (k & 8) ? (m[j] - tt) : (m[j] + tt);
            }
        }
        const float scale = (c == 16) ? (float)MULT_F : 1.f;
#pragma unroll
        for (int j = 0; j < 16; j++) g_M[(c - 12) * 256 + r * 16 + j] = m[j] * scale;
    }
}

// ---------------------------------------------------------------------------
// f32x2 packed helpers
// ---------------------------------------------------------------------------
__device__ __forceinline__ ull pk2(float lo, float hi) {
    ull r; asm("mov.b64 %0, {%1, %2};" : "=l"(r) : "f"(lo), "f"(hi)); return r;
}
__device__ __forceinline__ void unpk2(ull v, float& lo, float& hi) {
    asm("mov.b64 {%0, %1}, %2;" : "=f"(lo), "=f"(hi) : "l"(v));
}
__device__ __forceinline__ ull ffma2(ull a, ull b, ull c) {
    ull d; asm("fma.rn.f32x2 %0, %1, %2, %3;" : "=l"(d) : "l"(a), "l"(b), "l"(c)); return d;
}
__device__ __forceinline__ ull fmul2(ull a, ull b) {
    ull d; asm("mul.rn.f32x2 %0, %1, %2;" : "=l"(d) : "l"(a), "l"(b)); return d;
}
__device__ __forceinline__ ull fadd2(ull a, ull b) {
    ull d; asm("add.rn.f32x2 %0, %1, %2;" : "=l"(d) : "l"(a), "l"(b)); return d;
}

__device__ __forceinline__ void emb2(float a0, float a1, float* u) {
    float s0, c0, s1, c1;
    __sincosf(0.5f * a0, &s0, &c0);
    __sincosf(0.5f * a1, &s1, &c1);
    u[0] = c0 * c1; u[1] = c0 * s1; u[2] = s0 * c1; u[3] = s0 * s1;
}

// One W row complex dot: returns packed (yr, yi). K is compile-time.
template<int K>
__device__ __forceinline__ ull rowsum(const ull* __restrict__ W, const ull* pp) {
    const ulonglong2* row = (const ulonglong2*)(W + K * 16);
    const ulonglong2 w0 = row[0], w1 = row[1];
    ull ac0 = fmul2(w0.x, pp[0]),  ac2 = fmul2(w0.y, pp[1]);
    ull ac1 = fmul2(w1.x, pp[2]),  ac3 = fmul2(w1.y, pp[3]);
    const ulonglong2 w2 = row[2], w3 = row[3];
    ac0 = ffma2(w2.x, pp[4],  ac0); ac2 = ffma2(w2.y, pp[5],  ac2);
    ac1 = ffma2(w3.x, pp[6],  ac1); ac3 = ffma2(w3.y, pp[7],  ac3);
    const ulonglong2 w4 = row[4], w5 = row[5];
    ac0 = ffma2(w4.x, pp[8],  ac0); ac2 = ffma2(w4.y, pp[9],  ac2);
    ac1 = ffma2(w5.x, pp[10], ac1); ac3 = ffma2(w5.y, pp[11], ac3);
    const ulonglong2 w6 = row[6], w7 = row[7];
    ac0 = ffma2(w6.x, pp[12], ac0); ac2 = ffma2(w6.y, pp[13], ac2);
    ac1 = ffma2(w7.x, pp[14], ac1); ac3 = ffma2(w7.y, pp[15], ac3);
    return fadd2(fadd2(ac0, ac1), fadd2(ac2, ac3));
}

// Full circuit, 4 expvals. Fully unrolled; signs compile-time (o0<-k&8 ... o3<-k&1).
__device__ __forceinline__ void run4(const ull* __restrict__ W, const float* a, float* o) {
    float u[4], v[4];
    emb2(a[0], a[1], u); emb2(a[2], a[3], v);
    ull pp[16];
#pragma unroll
    for (int i = 0; i < 4; i++)
#pragma unroll
        for (int j = 0; j < 4; j++) { const float t = u[i] * v[j]; pp[i * 4 + j] = pk2(t, t); }

    float e0, e1, e2, e3;
    {
        float yr, yi; unpk2(rowsum<0>(W, pp), yr, yi);
        const float p = fmaf(yr, yr, yi * yi);
        e0 = p; e1 = p; e2 = p; e3 = p;
    }
#define ACC4(K) { float yr, yi; unpk2(rowsum<K>(W, pp), yr, yi);        \
        const float p = fmaf(yr, yr, yi * yi);                          \
        e0 = ((K) & 8) ? e0 - p : e0 + p;                               \
        e1 = ((K) & 4) ? e1 - p : e1 + p;                               \
        e2 = ((K) & 2) ? e2 - p : e2 + p;                               \
        e3 = ((K) & 1) ? e3 - p : e3 + p; }
    ACC4(1)  ACC4(2)  ACC4(3)  ACC4(4)  ACC4(5)  ACC4(6)  ACC4(7)
    ACC4(8)  ACC4(9)  ACC4(10) ACC4(11) ACC4(12) ACC4(13) ACC4(14) ACC4(15)
#undef ACC4
    o[0] = e0; o[1] = e1; o[2] = e2; o[3] = e3;
}

// Single expval via real quadratic form e = psi^T M psi. M in GLOBAL memory
// (warp-uniform broadcast __ldg; L1-resident). Dual fma chains.
__device__ __forceinline__ float run1(const float* __restrict__ M, const float* a) {
    float u[4], v[4];
    emb2(a[0], a[1], u); emb2(a[2], a[3], v);
    float psi[16];
#pragma unroll
    for (int i = 0; i < 4; i++)
#pragma unroll
        for (int j = 0; j < 4; j++) psi[i * 4 + j] = u[i] * v[j];
    ull pj[8];
#pragma unroll
    for (int j = 0; j < 8; j++) pj[j] = pk2(psi[2 * j], psi[2 * j + 1]);
    float eacc0 = 0.f, eacc1 = 0.f;
#pragma unroll 4
    for (int k = 0; k < 16; k++) {
        const ulonglong2* row = (const ulonglong2*)(M + k * 16);
        const ulonglong2 m0 = __ldg(row + 0), m1 = __ldg(row + 1);
        const ulonglong2 m2 = __ldg(row + 2), m3 = __ldg(row + 3);
        ull a0c = fmul2(m0.x, pj[0]);
        ull a1c = fmul2(m0.y, pj[1]);
        a0c = ffma2(m1.x, pj[2], a0c);
        a1c = ffma2(m1.y, pj[3], a1c);
        a0c = ffma2(m2.x, pj[4], a0c);
        a1c = ffma2(m2.y, pj[5], a1c);
        a0c = ffma2(m3.x, pj[6], a0c);
        a1c = ffma2(m3.y, pj[7], a1c);
        const ull s = fadd2(a0c, a1c);
        float lo, hi; unpk2(s, lo, hi);
        if (k & 1) eacc1 = fmaf(psi[k], lo + hi, eacc1);
        else       eacc0 = fmaf(psi[k], lo + hi, eacc0);
    }
    return eacc0 + eacc1;
}

// ---------------------------------------------------------------------------
// Main kernel: block = 32-element tile, warp w = circuit w of each stage,
// lane = element. Double-buffered exchange -> 5 barriers total.
// ---------------------------------------------------------------------------
__global__ __launch_bounds__(TPB, 7)
void vqc_warp(const float* __restrict__ x, float* __restrict__ out, int B) {
    __shared__ __align__(16) ull sW[12 * 256];     // 24 KB
    __shared__ float sH[2][32][17];                // 4.25 KB, stride-17 pad

    const int tid = threadIdx.x;
    {
        const float4* s1 = (const float4*)g_W12;
        float4* d1 = (float4*)sW;
        for (int i = tid; i < 12 * 128; i += TPB) d1[i] = s1[i];
    }

    const int e0 = blockIdx.x * 32;                 // tile base element
    for (int i = tid; i < 32 * 13; i += TPB) {
        const long gi = (long)e0 * 13 + i;
        if (gi < (long)B * 13) {
            const int e = i / 13, j = i - 13 * e;
            sH[0][e][j] = x[gi];
        }
    }
    __syncthreads();

    const int w = tid >> 5;   // warp = circuit index within stage
    const int e = tid & 31;   // lane  = element within tile
    const float* Mg = (const float*)g_M;
    float a[4], o[4];

    // Stage A: angles H = [0, x0..x12, 0, 0]; circuit w uses H[4w..4w+3]
#pragma unroll
    for (int i = 0; i < 4; i++) {
        const int j = 4 * w + i;
        a[i] = (j >= 1 && j <= 13) ? sH[0][e][j - 1] : 0.f;
    }
    run4(sW + w * 256, a, o);
#pragma unroll
    for (int i = 0; i < 4; i++) sH[1][e][4 * w + i] = o[i];
    __syncthreads();

    // Stage B (transposed wiring): read buf1, write buf0
#pragma unroll
    for (int i = 0; i < 4; i++) a[i] = sH[1][e][4 * i + w];
    run4(sW + (4 + w) * 256, a, o);
#pragma unroll
    for (int i = 0; i < 4; i++) sH[0][e][4 * w + i] = o[i];
    __syncthreads();

    // Stage C: read buf0, write buf1
#pragma unroll
    for (int i = 0; i < 4; i++) a[i] = sH[0][e][4 * i + w];
    run4(sW + (8 + w) * 256, a, o);
#pragma unroll
    for (int i = 0; i < 4; i++) sH[1][e][4 * w + i] = o[i];
    __syncthreads();

    // Stage D: read buf1, quadratic form w (M from global), write buf0
#pragma unroll
    for (int i = 0; i < 4; i++) a[i] = sH[1][e][4 * i + w];
    const float h4 = run1(Mg + w * 256, a);
    sH[0][e][w] = h4;
    __syncthreads();

    // Stage E: warp 0 only (MULT baked into M[4]); warp-uniform branch
    if (w != 0) return;
#pragma unroll
    for (int i = 0; i < 4; i++) a[i] = sH[0][e][i];
    const float r = run1(Mg + 4 * 256, a);
    if (e0 + e < B) out[e0 + e] = r;
}

extern "C" void kernel_launch(void* const* d_in, const int* in_sizes, int n_in,
                              void* d_out, int out_size) {
    const float* x     = (const float*)d_in[0];
    const float* theta = (const float*)d_in[1];
    if (n_in >= 2 && in_sizes[0] < in_sizes[1]) {
        x     = (const float*)d_in[1];
        theta = (const float*)d_in[0];
    }
    float* out = (float*)d_out;
    const int B = out_size;

    build_WM<<<17, 16>>>(theta);
    vqc_warp<<<(B + 31) / 32, TPB>>>(x, out, B);
}

// round 11
// speedup vs baseline: 1.0635x; 1.0077x over previous
#include <cuda_runtime.h>

#define TPB 128
typedef unsigned long long ull;

// MULT = pi - float-eps, folded into the stage-E quadratic form.
#define MULT_F (3.141592653589793 - 1.1920928955078125e-07)

// Precomputed (theta-dependent, batch-invariant), row-major broadcast layout:
__device__ __align__(16) float2 g_W12[12 * 256];   // unitaries, circuits 0..11 (stages A,B,C)
__device__ __align__(16) float  g_M[5 * 256];      // quadratic forms, circuits 12..16 (D,E)

// theta slice per circuit: A->theta[0], B->theta[3], C->theta[4], D->theta[1], E->theta[2][0]
__device__ __forceinline__ int circ_slice(int c) {
    if (c < 4)  return c;
    if (c < 8)  return 12 + (c - 4);
    if (c < 12) return 16 + (c - 8);
    if (c < 16) return 4 + (c - 12);
    return 8;
}

// One block per circuit (16 threads = 16 basis columns).
__global__ void build_WM(const float* __restrict__ theta) {
    const int c = blockIdx.x, col = threadIdx.x;
    const float* w = theta + circ_slice(c) * 48;

    float sr[16], si[16];
#pragma unroll
    for (int i = 0; i < 16; i++) { sr[i] = (i == col) ? 1.f : 0.f; si[i] = 0.f; }
#pragma unroll
    for (int l = 0; l < 4; l++) {
#pragma unroll
        for (int q = 0; q < 4; q++) {
            const float phi = w[(l * 4 + q) * 3 + 0];
            const float th  = w[(l * 4 + q) * 3 + 1];
            const float om  = w[(l * 4 + q) * 3 + 2];
            float ch, sh, ca, sa, cb, sb;
            __sincosf(0.5f * th, &sh, &ch);
            __sincosf(0.5f * (phi + om), &sa, &ca);
            __sincosf(0.5f * (phi - om), &sb, &cb);
            const float u00r =  ca * ch, u00i = -sa * ch;
            const float u01r = -cb * sh, u01i = -sb * sh;
            const float u10r =  cb * sh, u10i = -sb * sh;
            const float u11r =  ca * ch, u11i =  sa * ch;
            const int mask = 8 >> q;
#pragma unroll
            for (int k = 0; k < 16; k++) {
                if (k & mask) continue;
                const int k1 = k | mask;
                float ar = sr[k],  ai = si[k];
                float br = sr[k1], bi = si[k1];
                sr[k]  = u00r * ar - u00i * ai + u01r * br - u01i * bi;
                si[k]  = u00r * ai + u00i * ar + u01r * bi + u01i * br;
                sr[k1] = u10r * ar - u10i * ai + u11r * br - u11i * bi;
                si[k1] = u10r * ai + u10i * ar + u11r * bi + u11i * br;
            }
        }
        const int r = (l % 3) + 1;
#pragma unroll
        for (int q = 0; q < 4; q++) {
            const int cm = 8 >> q;
            const int tm = 8 >> ((q + r) & 3);
#pragma unroll
            for (int k = 0; k < 16; k++) {
                if ((k & cm) && !(k & tm)) {
                    const int k1 = k | tm;
                    float tr = sr[k], ti = si[k];
                    sr[k] = sr[k1]; si[k] = si[k1];
                    sr[k1] = tr;    si[k1] = ti;
                }
            }
        }
    }

    if (c < 12) {
#pragma unroll
        for (int k = 0; k < 16; k++)
            g_W12[c * 256 + k * 16 + col] = make_float2(sr[k], si[k]);
    } else {
        __shared__ float2 sWt[256];
#pragma unroll
        for (int k = 0; k < 16; k++) sWt[k * 16 + col] = make_float2(sr[k], si[k]);
        __syncthreads();
        const int r = col;
        float m[16];
#pragma unroll
        for (int j = 0; j < 16; j++) m[j] = 0.f;
#pragma unroll
        for (int k = 0; k < 16; k++) {
            const float2 wr = sWt[k * 16 + r];
#pragma unroll
            for (int j = 0; j < 16; j++) {
                const float2 wj = sWt[k * 16 + j];
                const float tt = wr.x * wj.x + wr.y * wj.y;
                m[j] = (k & 8) ? (m[j] - tt) : (m[j] + tt);
            }
        }
        const float scale = (c == 16) ? (float)MULT_F : 1.f;
#pragma unroll
        for (int j = 0; j < 16; j++) g_M[(c - 12) * 256 + r * 16 + j] = m[j] * scale;
    }
}

// ---------------------------------------------------------------------------
// f32x2 packed helpers
// ---------------------------------------------------------------------------
__device__ __forceinline__ ull pk2(float lo, float hi) {
    ull r; asm("mov.b64 %0, {%1, %2};" : "=l"(r) : "f"(lo), "f"(hi)); return r;
}
__device__ __forceinline__ void unpk2(ull v, float& lo, float& hi) {
    asm("mov.b64 {%0, %1}, %2;" : "=f"(lo), "=f"(hi) : "l"(v));
}
__device__ __forceinline__ ull ffma2(ull a, ull b, ull c) {
    ull d; asm("fma.rn.f32x2 %0, %1, %2, %3;" : "=l"(d) : "l"(a), "l"(b), "l"(c)); return d;
}
__device__ __forceinline__ ull fmul2(ull a, ull b) {
    ull d; asm("mul.rn.f32x2 %0, %1, %2;" : "=l"(d) : "l"(a), "l"(b)); return d;
}
__device__ __forceinline__ ull fadd2(ull a, ull b) {
    ull d; asm("add.rn.f32x2 %0, %1, %2;" : "=l"(d) : "l"(a), "l"(b)); return d;
}

__device__ __forceinline__ void emb2(float a0, float a1, float* u) {
    float s0, c0, s1, c1;
    __sincosf(0.5f * a0, &s0, &c0);
    __sincosf(0.5f * a1, &s1, &c1);
    u[0] = c0 * c1; u[1] = c0 * s1; u[2] = s0 * c1; u[3] = s0 * s1;
}

// Full circuit, 4 expvals. W rows packed as f32x2 complex, broadcast reads.
__device__ __forceinline__ void run4(const ull* __restrict__ W, const float* a, float* o) {
    float u[4], v[4];
    emb2(a[0], a[1], u); emb2(a[2], a[3], v);
    ull pp[16];
#pragma unroll
    for (int i = 0; i < 4; i++)
#pragma unroll
        for (int j = 0; j < 4; j++) { const float t = u[i] * v[j]; pp[i * 4 + j] = pk2(t, t); }
    float e0 = 0.f, e1 = 0.f, e2 = 0.f, e3 = 0.f;
#pragma unroll 4
    for (int k = 0; k < 16; k++) {
        const ulonglong2* row = (const ulonglong2*)(W + k * 16);
        const ulonglong2 w0 = row[0], w1 = row[1];
        ull ac0 = fmul2(w0.x, pp[0]), ac2 = fmul2(w0.y, pp[1]);
        ull ac1 = fmul2(w1.x, pp[2]), ac3 = fmul2(w1.y, pp[3]);
#pragma unroll
        for (int jj = 2; jj < 8; jj += 2) {
            const ulonglong2 wA = row[jj], wB = row[jj + 1];
            ac0 = ffma2(wA.x, pp[2 * jj],     ac0);
            ac2 = ffma2(wA.y, pp[2 * jj + 1], ac2);
            ac1 = ffma2(wB.x, pp[2 * jj + 2], ac1);
            ac3 = ffma2(wB.y, pp[2 * jj + 3], ac3);
        }
        const ull s = fadd2(fadd2(ac0, ac1), fadd2(ac2, ac3));
        float yr, yi; unpk2(s, yr, yi);
        const float p = fmaf(yr, yr, yi * yi);
        e0 = (k & 8) ? (e0 - p) : (e0 + p);
        e1 = (k & 4) ? (e1 - p) : (e1 + p);
        e2 = (k & 2) ? (e2 - p) : (e2 + p);
        e3 = (k & 1) ? (e3 - p) : (e3 + p);
    }
    o[0] = e0; o[1] = e1; o[2] = e2; o[3] = e3;
}

// Single expval via real quadratic form e = psi^T M psi (smem broadcast reads).
__device__ __forceinline__ float run1(const float* __restrict__ M, const float* a) {
    float u[4], v[4];
    emb2(a[0], a[1], u); emb2(a[2], a[3], v);
    float psi[16];
#pragma unroll
    for (int i = 0; i < 4; i++)
#pragma unroll
        for (int j = 0; j < 4; j++) psi[i * 4 + j] = u[i] * v[j];
    ull pj[8];
#pragma unroll
    for (int j = 0; j < 8; j++) pj[j] = pk2(psi[2 * j], psi[2 * j + 1]);
    float eacc0 = 0.f, eacc1 = 0.f;
#pragma unroll 4
    for (int k = 0; k < 16; k++) {
        const ulonglong2* row = (const ulonglong2*)(M + k * 16);
        const ulonglong2 m0 = row[0], m1 = row[1], m2 = row[2], m3 = row[3];
        ull a0c = fmul2(m0.x, pj[0]);
        ull a1c = fmul2(m0.y, pj[1]);
        a0c = ffma2(m1.x, pj[2], a0c);
        a1c = ffma2(m1.y, pj[3], a1c);
        a0c = ffma2(m2.x, pj[4], a0c);
        a1c = ffma2(m2.y, pj[5], a1c);
        a0c = ffma2(m3.x, pj[6], a0c);
        a1c = ffma2(m3.y, pj[7], a1c);
        const ull s = fadd2(a0c, a1c);
        float lo, hi; unpk2(s, lo, hi);
        if (k & 1) eacc1 = fmaf(psi[k], lo + hi, eacc1);
        else       eacc0 = fmaf(psi[k], lo + hi, eacc0);
    }
    return eacc0 + eacc1;
}

// ---------------------------------------------------------------------------
// Main kernel: block = 32-element tile, warp w = circuit w of each stage,
// lane = element. Double-buffered exchange: 5 barriers after the const load.
// ---------------------------------------------------------------------------
__global__ __launch_bounds__(TPB, 7)
void vqc_warp(const float* __restrict__ x, float* __restrict__ out, int B) {
    __shared__ __align__(16) ull   sW[12 * 256];   // 24 KB
    __shared__ __align__(16) float sM[5 * 256];    // 5 KB
    __shared__ float sH[2][32][17];                // 4.25 KB, stride-17 pad

    const int tid = threadIdx.x;
    {
        const float4* s1 = (const float4*)g_W12;
        float4* d1 = (float4*)sW;
        for (int i = tid; i < 12 * 128; i += TPB) d1[i] = s1[i];
        const float4* s2 = (const float4*)g_M;
        float4* d2 = (float4*)sM;
        for (int i = tid; i < 5 * 64; i += TPB) d2[i] = s2[i];
    }

    const int e0 = blockIdx.x * 32;                 // tile base element
    for (int i = tid; i < 32 * 13; i += TPB) {
        const long gi = (long)e0 * 13 + i;
        if (gi < (long)B * 13) {
            const int e = i / 13, j = i - 13 * e;
            sH[0][e][j] = x[gi];
        }
    }
    __syncthreads();

    const int w = tid >> 5;   // warp = circuit index within stage
    const int e = tid & 31;   // lane  = element within tile
    float a[4], o[4];

    // Stage A: angles H = [0, x0..x12, 0, 0]; circuit w uses H[4w..4w+3]
#pragma unroll
    for (int i = 0; i < 4; i++) {
        const int j = 4 * w + i;
        a[i] = (j >= 1 && j <= 13) ? sH[0][e][j - 1] : 0.f;
    }
    run4(sW + w * 256, a, o);
#pragma unroll
    for (int i = 0; i < 4; i++) sH[1][e][4 * w + i] = o[i];
    __syncthreads();

    // Stage B (transposed wiring): read buf1, write buf0
#pragma unroll
    for (int i = 0; i < 4; i++) a[i] = sH[1][e][4 * i + w];
    run4(sW + (4 + w) * 256, a, o);
#pragma unroll
    for (int i = 0; i < 4; i++) sH[0][e][4 * w + i] = o[i];
    __syncthreads();

    // Stage C: read buf0, write buf1
#pragma unroll
    for (int i = 0; i < 4; i++) a[i] = sH[0][e][4 * i + w];
    run4(sW + (8 + w) * 256, a, o);
#pragma unroll
    for (int i = 0; i < 4; i++) sH[1][e][4 * w + i] = o[i];
    __syncthreads();

    // Stage D: read buf1, quadratic form w, write buf0
#pragma unroll
    for (int i = 0; i < 4; i++) a[i] = sH[1][e][4 * i + w];
    const float h4 = run1(sM + w * 256, a);
    sH[0][e][w] = h4;
    __syncthreads();

    // Stage E: warp 0 only (MULT baked into sM[4]); warp-uniform branch
    if (w != 0) return;
#pragma unroll
    for (int i = 0; i < 4; i++) a[i] = sH[0][e][i];
    const float r = run1(sM + 4 * 256, a);
    if (e0 + e < B) out[e0 + e] = r;
}

extern "C" void kernel_launch(void* const* d_in, const int* in_sizes, int n_in,
                              void* d_out, int out_size) {
    const float* x     = (const float*)d_in[0];
    const float* theta = (const float*)d_in[1];
    if (n_in >= 2 && in_sizes[0] < in_sizes[1]) {
        x     = (const float*)d_in[1];
        theta = (const float*)d_in[0];
    }
    float* out = (float*)d_out;
    const int B = out_size;

    build_WM<<<17, 16>>>(theta);
    vqc_warp<<<(B + 31) / 32, TPB>>>(x, out, B);
}

// round 12
// speedup vs baseline: 1.1207x; 1.0538x over previous
#include <cuda_runtime.h>

#define TPB 128
typedef unsigned long long ull;

// MULT = pi - float-eps, folded into the stage-E quadratic form.
#define MULT_F (3.141592653589793 - 1.1920928955078125e-07)

// Precomputed (theta-dependent, batch-invariant):
//  g_Wf : stages A,B,C (12 circuits), re/im split per k-row:
//         float[c*512 + k*32 + 0..15]  = Re(W[k][j])
//         float[c*512 + k*32 + 16..31] = Im(W[k][j])
//  g_M  : quadratic forms, circuits 12..16 (D,E); E pre-scaled by MULT.
__device__ __align__(16) float g_Wf[12 * 512];
__device__ __align__(16) float g_M[5 * 256];

// theta slice per circuit: A->theta[0], B->theta[3], C->theta[4], D->theta[1], E->theta[2][0]
__device__ __forceinline__ int circ_slice(int c) {
    if (c < 4)  return c;
    if (c < 8)  return 12 + (c - 4);
    if (c < 12) return 16 + (c - 8);
    if (c < 16) return 4 + (c - 12);
    return 8;
}

// One block per circuit (16 threads = 16 basis columns).
__global__ void build_WM(const float* __restrict__ theta) {
    const int c = blockIdx.x, col = threadIdx.x;
    const float* w = theta + circ_slice(c) * 48;

    float sr[16], si[16];
#pragma unroll
    for (int i = 0; i < 16; i++) { sr[i] = (i == col) ? 1.f : 0.f; si[i] = 0.f; }
#pragma unroll
    for (int l = 0; l < 4; l++) {
#pragma unroll
        for (int q = 0; q < 4; q++) {
            const float phi = w[(l * 4 + q) * 3 + 0];
            const float th  = w[(l * 4 + q) * 3 + 1];
            const float om  = w[(l * 4 + q) * 3 + 2];
            float ch, sh, ca, sa, cb, sb;
            __sincosf(0.5f * th, &sh, &ch);
            __sincosf(0.5f * (phi + om), &sa, &ca);
            __sincosf(0.5f * (phi - om), &sb, &cb);
            const float u00r =  ca * ch, u00i = -sa * ch;
            const float u01r = -cb * sh, u01i = -sb * sh;
            const float u10r =  cb * sh, u10i = -sb * sh;
            const float u11r =  ca * ch, u11i =  sa * ch;
            const int mask = 8 >> q;
#pragma unroll
            for (int k = 0; k < 16; k++) {
                if (k & mask) continue;
                const int k1 = k | mask;
                float ar = sr[k],  ai = si[k];
                float br = sr[k1], bi = si[k1];
                sr[k]  = u00r * ar - u00i * ai + u01r * br - u01i * bi;
                si[k]  = u00r * ai + u00i * ar + u01r * bi + u01i * br;
                sr[k1] = u10r * ar - u10i * ai + u11r * br - u11i * bi;
                si[k1] = u10r * ai + u10i * ar + u11r * bi + u11i * br;
            }
        }
        const int r = (l % 3) + 1;
#pragma unroll
        for (int q = 0; q < 4; q++) {
            const int cm = 8 >> q;
            const int tm = 8 >> ((q + r) & 3);
#pragma unroll
            for (int k = 0; k < 16; k++) {
                if ((k & cm) && !(k & tm)) {
                    const int k1 = k | tm;
                    float tr = sr[k], ti = si[k];
                    sr[k] = sr[k1]; si[k] = si[k1];
                    sr[k1] = tr;    si[k1] = ti;
                }
            }
        }
    }

    if (c < 12) {
#pragma unroll
        for (int k = 0; k < 16; k++) {
            g_Wf[c * 512 + k * 32 + col]      = sr[k];   // re
            g_Wf[c * 512 + k * 32 + 16 + col] = si[k];   // im
        }
    } else {
        __shared__ float2 sWt[256];
#pragma unroll
        for (int k = 0; k < 16; k++) sWt[k * 16 + col] = make_float2(sr[k], si[k]);
        __syncthreads();
        const int r = col;
        float m[16];
#pragma unroll
        for (int j = 0; j < 16; j++) m[j] = 0.f;
#pragma unroll
        for (int k = 0; k < 16; k++) {
            const float2 wr = sWt[k * 16 + r];
#pragma unroll
            for (int j = 0; j < 16; j++) {
                const float2 wj = sWt[k * 16 + j];
                const float tt = wr.x * wj.x + wr.y * wj.y;
                m[j] = (k & 8) ? (m[j] - tt) : (m[j] + tt);
            }
        }
        const float scale = (c == 16) ? (float)MULT_F : 1.f;
#pragma unroll
        for (int j = 0; j < 16; j++) g_M[(c - 12) * 256 + r * 16 + j] = m[j] * scale;
    }
}

// ---------------------------------------------------------------------------
// f32x2 packed helpers
// ---------------------------------------------------------------------------
__device__ __forceinline__ ull pk2(float lo, float hi) {
    ull r; asm("mov.b64 %0, {%1, %2};" : "=l"(r) : "f"(lo), "f"(hi)); return r;
}
__device__ __forceinline__ void unpk2(ull v, float& lo, float& hi) {
    asm("mov.b64 {%0, %1}, %2;" : "=f"(lo), "=f"(hi) : "l"(v));
}
__device__ __forceinline__ ull ffma2(ull a, ull b, ull c) {
    ull d; asm("fma.rn.f32x2 %0, %1, %2, %3;" : "=l"(d) : "l"(a), "l"(b), "l"(c)); return d;
}
__device__ __forceinline__ ull fmul2(ull a, ull b) {
    ull d; asm("mul.rn.f32x2 %0, %1, %2;" : "=l"(d) : "l"(a), "l"(b)); return d;
}
__device__ __forceinline__ ull fadd2(ull a, ull b) {
    ull d; asm("add.rn.f32x2 %0, %1, %2;" : "=l"(d) : "l"(a), "l"(b)); return d;
}

// j-pair packed psi from 4 angles:
//   pj[i*2]   = (u_i v0, u_i v1),  pj[i*2+1] = (u_i v2, u_i v3)
__device__ __forceinline__ void emb_pj(const float* a, ull* pj) {
    float s0, c0, s1, c1, s2, c2, s3, c3;
    __sincosf(0.5f * a[0], &s0, &c0);
    __sincosf(0.5f * a[1], &s1, &c1);
    __sincosf(0.5f * a[2], &s2, &c2);
    __sincosf(0.5f * a[3], &s3, &c3);
    const float u[4] = { c0 * c1, c0 * s1, s0 * c1, s0 * s1 };
    const float v[4] = { c2 * c3, c2 * s3, s2 * c3, s2 * s3 };
#pragma unroll
    for (int i = 0; i < 4; i++) {
        pj[i * 2 + 0] = pk2(u[i] * v[0], u[i] * v[1]);
        pj[i * 2 + 1] = pk2(u[i] * v[2], u[i] * v[3]);
    }
}

// Full circuit, 4 expvals. W = re/im split rows; pj = j-pair packed psi.
__device__ __forceinline__ void run4(const ull* __restrict__ W, const float* a, float* o) {
    ull pj[8];
    emb_pj(a, pj);
    float e0 = 0.f, e1 = 0.f, e2 = 0.f, e3 = 0.f;
#pragma unroll 4
    for (int k = 0; k < 16; k++) {
        const ulonglong2* R = (const ulonglong2*)(W + k * 16);
        const ulonglong2 r0 = R[0], r1 = R[1], r2 = R[2], r3 = R[3]; // re pairs
        ull ra0 = fmul2(r0.x, pj[0]), ra1 = fmul2(r0.y, pj[1]);
        ra0 = ffma2(r1.x, pj[2], ra0); ra1 = ffma2(r1.y, pj[3], ra1);
        ra0 = ffma2(r2.x, pj[4], ra0); ra1 = ffma2(r2.y, pj[5], ra1);
        ra0 = ffma2(r3.x, pj[6], ra0); ra1 = ffma2(r3.y, pj[7], ra1);
        const ulonglong2 i0 = R[4], i1 = R[5], i2 = R[6], i3 = R[7]; // im pairs
        ull ia0 = fmul2(i0.x, pj[0]), ia1 = fmul2(i0.y, pj[1]);
        ia0 = ffma2(i1.x, pj[2], ia0); ia1 = ffma2(i1.y, pj[3], ia1);
        ia0 = ffma2(i2.x, pj[4], ia0); ia1 = ffma2(i2.y, pj[5], ia1);
        ia0 = ffma2(i3.x, pj[6], ia0); ia1 = ffma2(i3.y, pj[7], ia1);
        float lo, hi;
        unpk2(fadd2(ra0, ra1), lo, hi); const float yr = lo + hi;
        unpk2(fadd2(ia0, ia1), lo, hi); const float yi = lo + hi;
        const float p = fmaf(yr, yr, yi * yi);
        e0 = (k & 8) ? (e0 - p) : (e0 + p);
        e1 = (k & 4) ? (e1 - p) : (e1 + p);
        e2 = (k & 2) ? (e2 - p) : (e2 + p);
        e3 = (k & 1) ? (e3 - p) : (e3 + p);
    }
    o[0] = e0; o[1] = e1; o[2] = e2; o[3] = e3;
}

// Single expval via real quadratic form e = psi^T M psi (smem broadcast reads).
__device__ __forceinline__ float run1(const float* __restrict__ M, const float* a) {
    float s0, c0, s1, c1, s2, c2, s3, c3;
    __sincosf(0.5f * a[0], &s0, &c0);
    __sincosf(0.5f * a[1], &s1, &c1);
    __sincosf(0.5f * a[2], &s2, &c2);
    __sincosf(0.5f * a[3], &s3, &c3);
    const float u[4] = { c0 * c1, c0 * s1, s0 * c1, s0 * s1 };
    const float v[4] = { c2 * c3, c2 * s3, s2 * c3, s2 * s3 };
    float psi[16];
#pragma unroll
    for (int i = 0; i < 4; i++)
#pragma unroll
        for (int j = 0; j < 4; j++) psi[i * 4 + j] = u[i] * v[j];
    ull pj[8];
#pragma unroll
    for (int j = 0; j < 8; j++) pj[j] = pk2(psi[2 * j], psi[2 * j + 1]);
    float eacc0 = 0.f, eacc1 = 0.f;
#pragma unroll 4
    for (int k = 0; k < 16; k++) {
        const ulonglong2* row = (const ulonglong2*)(M + k * 16);
        const ulonglong2 m0 = row[0], m1 = row[1], m2 = row[2], m3 = row[3];
        ull a0c = fmul2(m0.x, pj[0]);
        ull a1c = fmul2(m0.y, pj[1]);
        a0c = ffma2(m1.x, pj[2], a0c);
        a1c = ffma2(m1.y, pj[3], a1c);
        a0c = ffma2(m2.x, pj[4], a0c);
        a1c = ffma2(m2.y, pj[5], a1c);
        a0c = ffma2(m3.x, pj[6], a0c);
        a1c = ffma2(m3.y, pj[7], a1c);
        const ull s = fadd2(a0c, a1c);
        float lo, hi; unpk2(s, lo, hi);
        if (k & 1) eacc1 = fmaf(psi[k], lo + hi, eacc1);
        else       eacc0 = fmaf(psi[k], lo + hi, eacc0);
    }
    return eacc0 + eacc1;
}

// ---------------------------------------------------------------------------
// Main kernel: block = 32-element tile, warp w = circuit w of each stage,
// lane = element. All W/M reads are full-warp broadcasts. (R7 skeleton.)
// ---------------------------------------------------------------------------
__global__ __launch_bounds__(TPB, 7)
void vqc_warp(const float* __restrict__ x, float* __restrict__ out, int B) {
    __shared__ __align__(16) ull   sW[12 * 256];   // 24 KB
    __shared__ __align__(16) float sM[5 * 256];    // 5 KB
    __shared__ float sH[32][17];                   // 2.1 KB, stride-17 pad

    const int tid = threadIdx.x;
    {
        const float4* s1 = (const float4*)g_Wf;
        float4* d1 = (float4*)sW;
        for (int i = tid; i < 12 * 128; i += TPB) d1[i] = s1[i];
        const float4* s2 = (const float4*)g_M;
        float4* d2 = (float4*)sM;
        for (int i = tid; i < 5 * 64; i += TPB) d2[i] = s2[i];
    }

    const int e0 = blockIdx.x * 32;                 // tile base element
    for (int i = tid; i < 32 * 13; i += TPB) {
        const long gi = (long)e0 * 13 + i;
        if (gi < (long)B * 13) {
            const int e = i / 13, j = i - 13 * e;
            sH[e][j] = x[gi];
        }
    }
    __syncthreads();

    const int w = tid >> 5;   // warp = circuit index within stage
    const int e = tid & 31;   // lane  = element within tile
    float a[4], o[4];

    // Stage A angles: H = [0, x0..x12, 0, 0]; circuit w uses H[4w..4w+3]
#pragma unroll
    for (int i = 0; i < 4; i++) {
        const int j = 4 * w + i;
        a[i] = (j >= 1 && j <= 13) ? sH[e][j - 1] : 0.f;
    }
    __syncthreads();

    // Stage A
    run4(sW + w * 256, a, o);
#pragma unroll
    for (int i = 0; i < 4; i++) sH[e][4 * w + i] = o[i];
    __syncthreads();
#pragma unroll
    for (int i = 0; i < 4; i++) a[i] = sH[e][4 * i + w];    // transposed wiring
    __syncthreads();

    // Stage B
    run4(sW + (4 + w) * 256, a, o);
#pragma unroll
    for (int i = 0; i < 4; i++) sH[e][4 * w + i] = o[i];
    __syncthreads();
#pragma unroll
    for (int i = 0; i < 4; i++) a[i] = sH[e][4 * i + w];
    __syncthreads();

    // Stage C
    run4(sW + (8 + w) * 256, a, o);
#pragma unroll
    for (int i = 0; i < 4; i++) sH[e][4 * w + i] = o[i];
    __syncthreads();
#pragma unroll
    for (int i = 0; i < 4; i++) a[i] = sH[e][4 * i + w];
    __syncthreads();

    // Stage D: quadratic form w
    const float h4 = run1(sM + w * 256, a);
    sH[e][w] = h4;
    __syncthreads();

    // Stage E: warp 0 only (MULT baked into sM[4]); warp-uniform branch
    if (w != 0) return;
#pragma unroll
    for (int i = 0; i < 4; i++) a[i] = sH[e][i];
    const float r = run1(sM + 4 * 256, a);
    if (e0 + e < B) out[e0 + e] = r;
}

extern "C" void kernel_launch(void* const* d_in, const int* in_sizes, int n_in,
                              void* d_out, int out_size) {
    const float* x     = (const float*)d_in[0];
    const float* theta = (const float*)d_in[1];
    if (n_in >= 2 && in_sizes[0] < in_sizes[1]) {
        x     = (const float*)d_in[1];
        theta = (const float*)d_in[0];
    }
    float* out = (float*)d_out;
    const int B = out_size;

    build_WM<<<17, 16>>>(theta);
    vqc_warp<<<(B + 31) / 32, TPB>>>(x, out, B);
}

// round 13
// speedup vs baseline: 1.1241x; 1.0031x over previous
#include <cuda_runtime.h>

#define TPB 128
typedef unsigned long long ull;

// MULT = pi - float-eps, folded into the stage-E quadratic form.
#define MULT_F (3.141592653589793 - 1.1920928955078125e-07)

// Precomputed (theta-dependent, batch-invariant), row-major broadcast layout:
__device__ __align__(16) float2 g_W12[12 * 256];   // unitaries, circuits 0..11 (stages A,B,C)
__device__ __align__(16) float  g_M[5 * 256];      // quadratic forms, circuits 12..16 (D,E)

// theta slice per circuit: A->theta[0], B->theta[3], C->theta[4], D->theta[1], E->theta[2][0]
__device__ __forceinline__ int circ_slice(int c) {
    if (c < 4)  return c;
    if (c < 8)  return 12 + (c - 4);
    if (c < 12) return 16 + (c - 8);
    if (c < 16) return 4 + (c - 12);
    return 8;
}

// One block per circuit (16 threads = 16 basis columns).
__global__ void build_WM(const float* __restrict__ theta) {
    const int c = blockIdx.x, col = threadIdx.x;
    const float* w = theta + circ_slice(c) * 48;

    float sr[16], si[16];
#pragma unroll
    for (int i = 0; i < 16; i++) { sr[i] = (i == col) ? 1.f : 0.f; si[i] = 0.f; }
#pragma unroll
    for (int l = 0; l < 4; l++) {
#pragma unroll
        for (int q = 0; q < 4; q++) {
            const float phi = w[(l * 4 + q) * 3 + 0];
            const float th  = w[(l * 4 + q) * 3 + 1];
            const float om  = w[(l * 4 + q) * 3 + 2];
            float ch, sh, ca, sa, cb, sb;
            __sincosf(0.5f * th, &sh, &ch);
            __sincosf(0.5f * (phi + om), &sa, &ca);
            __sincosf(0.5f * (phi - om), &sb, &cb);
            const float u00r =  ca * ch, u00i = -sa * ch;
            const float u01r = -cb * sh, u01i = -sb * sh;
            const float u10r =  cb * sh, u10i = -sb * sh;
            const float u11r =  ca * ch, u11i =  sa * ch;
            const int mask = 8 >> q;
#pragma unroll
            for (int k = 0; k < 16; k++) {
                if (k & mask) continue;
                const int k1 = k | mask;
                float ar = sr[k],  ai = si[k];
                float br = sr[k1], bi = si[k1];
                sr[k]  = u00r * ar - u00i * ai + u01r * br - u01i * bi;
                si[k]  = u00r * ai + u00i * ar + u01r * bi + u01i * br;
                sr[k1] = u10r * ar - u10i * ai + u11r * br - u11i * bi;
                si[k1] = u10r * ai + u10i * ar + u11r * bi + u11i * br;
            }
        }
        const int r = (l % 3) + 1;
#pragma unroll
        for (int q = 0; q < 4; q++) {
            const int cm = 8 >> q;
            const int tm = 8 >> ((q + r) & 3);
#pragma unroll
            for (int k = 0; k < 16; k++) {
                if ((k & cm) && !(k & tm)) {
                    const int k1 = k | tm;
                    float tr = sr[k], ti = si[k];
                    sr[k] = sr[k1]; si[k] = si[k1];
                    sr[k1] = tr;    si[k1] = ti;
                }
            }
        }
    }

    if (c < 12) {
#pragma unroll
        for (int k = 0; k < 16; k++)
            g_W12[c * 256 + k * 16 + col] = make_float2(sr[k], si[k]);
    } else {
        __shared__ float2 sWt[256];
#pragma unroll
        for (int k = 0; k < 16; k++) sWt[k * 16 + col] = make_float2(sr[k], si[k]);
        __syncthreads();
        const int r = col;
        float m[16];
#pragma unroll
        for (int j = 0; j < 16; j++) m[j] = 0.f;
#pragma unroll
        for (int k = 0; k < 16; k++) {
            const float2 wr = sWt[k * 16 + r];
#pragma unroll
            for (int j = 0; j < 16; j++) {
                const float2 wj = sWt[k * 16 + j];
                const float tt = wr.x * wj.x + wr.y * wj.y;
                m[j] = (k & 8) ? (m[j] - tt) : (m[j] + tt);
            }
        }
        const float scale = (c == 16) ? (float)MULT_F : 1.f;
#pragma unroll
        for (int j = 0; j < 16; j++) g_M[(c - 12) * 256 + r * 16 + j] = m[j] * scale;
    }
    // PDL: allow the dependent (main) kernel to start scheduling.
    asm volatile("griddepcontrol.launch_dependents;" ::: "memory");
}

// ---------------------------------------------------------------------------
// f32x2 packed helpers
// ---------------------------------------------------------------------------
__device__ __forceinline__ ull pk2(float lo, float hi) {
    ull r; asm("mov.b64 %0, {%1, %2};" : "=l"(r) : "f"(lo), "f"(hi)); return r;
}
__device__ __forceinline__ void unpk2(ull v, float& lo, float& hi) {
    asm("mov.b64 {%0, %1}, %2;" : "=f"(lo), "=f"(hi) : "l"(v));
}
__device__ __forceinline__ ull ffma2(ull a, ull b, ull c) {
    ull d; asm("fma.rn.f32x2 %0, %1, %2, %3;" : "=l"(d) : "l"(a), "l"(b), "l"(c)); return d;
}
__device__ __forceinline__ ull fmul2(ull a, ull b) {
    ull d; asm("mul.rn.f32x2 %0, %1, %2;" : "=l"(d) : "l"(a), "l"(b)); return d;
}
__device__ __forceinline__ ull fadd2(ull a, ull b) {
    ull d; asm("add.rn.f32x2 %0, %1, %2;" : "=l"(d) : "l"(a), "l"(b)); return d;
}

__device__ __forceinline__ void emb2(float a0, float a1, float* u) {
    float s0, c0, s1, c1;
    __sincosf(0.5f * a0, &s0, &c0);
    __sincosf(0.5f * a1, &s1, &c1);
    u[0] = c0 * c1; u[1] = c0 * s1; u[2] = s0 * c1; u[3] = s0 * s1;
}

// Full circuit, 4 expvals. W rows packed as f32x2 complex, broadcast reads. (R7 form)
__device__ __forceinline__ void run4(const ull* __restrict__ W, const float* a, float* o) {
    float u[4], v[4];
    emb2(a[0], a[1], u); emb2(a[2], a[3], v);
    ull pp[16];
#pragma unroll
    for (int i = 0; i < 4; i++)
#pragma unroll
        for (int j = 0; j < 4; j++) { const float t = u[i] * v[j]; pp[i * 4 + j] = pk2(t, t); }
    float e0 = 0.f, e1 = 0.f, e2 = 0.f, e3 = 0.f;
#pragma unroll 4
    for (int k = 0; k < 16; k++) {
        const ulonglong2* row = (const ulonglong2*)(W + k * 16);
        const ulonglong2 w0 = row[0], w1 = row[1];
        ull ac0 = fmul2(w0.x, pp[0]), ac2 = fmul2(w0.y, pp[1]);
        ull ac1 = fmul2(w1.x, pp[2]), ac3 = fmul2(w1.y, pp[3]);
#pragma unroll
        for (int jj = 2; jj < 8; jj += 2) {
            const ulonglong2 wA = row[jj], wB = row[jj + 1];
            ac0 = ffma2(wA.x, pp[2 * jj],     ac0);
            ac2 = ffma2(wA.y, pp[2 * jj + 1], ac2);
            ac1 = ffma2(wB.x, pp[2 * jj + 2], ac1);
            ac3 = ffma2(wB.y, pp[2 * jj + 3], ac3);
        }
        const ull s = fadd2(fadd2(ac0, ac1), fadd2(ac2, ac3));
        float yr, yi; unpk2(s, yr, yi);
        const float p = fmaf(yr, yr, yi * yi);
        e0 = (k & 8) ? (e0 - p) : (e0 + p);
        e1 = (k & 4) ? (e1 - p) : (e1 + p);
        e2 = (k & 2) ? (e2 - p) : (e2 + p);
        e3 = (k & 1) ? (e3 - p) : (e3 + p);
    }
    o[0] = e0; o[1] = e1; o[2] = e2; o[3] = e3;
}

// Stage-A specialization: a0 == 0 -> only columns 0..7 active. (validated R5)
__device__ __forceinline__ void run4_half(const ull* __restrict__ W,
                                          float a1, float a2, float a3, float* o) {
    float s1, c1, v[4];
    __sincosf(0.5f * a1, &s1, &c1);
    emb2(a2, a3, v);
    ull pp[8];
#pragma unroll
    for (int j = 0; j < 4; j++) {
        const float t0 = c1 * v[j], t1 = s1 * v[j];
        pp[j] = pk2(t0, t0); pp[4 + j] = pk2(t1, t1);
    }
    float e0 = 0.f, e1 = 0.f, e2 = 0.f, e3 = 0.f;
#pragma unroll 4
    for (int k = 0; k < 16; k++) {
        const ulonglong2* row = (const ulonglong2*)(W + k * 16);
        const ulonglong2 w0 = row[0], w1 = row[1], w2 = row[2], w3 = row[3];
        ull a0c = fmul2(w0.x, pp[0]);
        ull a1c = fmul2(w0.y, pp[1]);
        a0c = ffma2(w1.x, pp[2], a0c);
        a1c = ffma2(w1.y, pp[3], a1c);
        a0c = ffma2(w2.x, pp[4], a0c);
        a1c = ffma2(w2.y, pp[5], a1c);
        a0c = ffma2(w3.x, pp[6], a0c);
        a1c = ffma2(w3.y, pp[7], a1c);
        const ull s = fadd2(a0c, a1c);
        float yr, yi; unpk2(s, yr, yi);
        const float p = fmaf(yr, yr, yi * yi);
        e0 = (k & 8) ? (e0 - p) : (e0 + p);
        e1 = (k & 4) ? (e1 - p) : (e1 + p);
        e2 = (k & 2) ? (e2 - p) : (e2 + p);
        e3 = (k & 1) ? (e3 - p) : (e3 + p);
    }
    o[0] = e0; o[1] = e1; o[2] = e2; o[3] = e3;
}

// Stage-A specialization: a2 == a3 == 0 -> only columns {0,4,8,12}. (validated R5)
__device__ __forceinline__ void run4_sparse(const ull* __restrict__ W,
                                            float a0, float a1, float* o) {
    float u[4];
    emb2(a0, a1, u);
    ull pu[4];
#pragma unroll
    for (int i = 0; i < 4; i++) pu[i] = pk2(u[i], u[i]);
    float e0 = 0.f, e1 = 0.f, e2 = 0.f, e3 = 0.f;
#pragma unroll 4
    for (int k = 0; k < 16; k++) {
        const ull* row = W + k * 16;
        ull a0c = fmul2(row[0], pu[0]);
        ull a1c = fmul2(row[4], pu[1]);
        a0c = ffma2(row[8],  pu[2], a0c);
        a1c = ffma2(row[12], pu[3], a1c);
        const ull s = fadd2(a0c, a1c);
        float yr, yi; unpk2(s, yr, yi);
        const float p = fmaf(yr, yr, yi * yi);
        e0 = (k & 8) ? (e0 - p) : (e0 + p);
        e1 = (k & 4) ? (e1 - p) : (e1 + p);
        e2 = (k & 2) ? (e2 - p) : (e2 + p);
        e3 = (k & 1) ? (e3 - p) : (e3 + p);
    }
    o[0] = e0; o[1] = e1; o[2] = e2; o[3] = e3;
}

// Single expval via real quadratic form e = psi^T M psi (smem broadcast reads).
__device__ __forceinline__ float run1(const float* __restrict__ M, const float* a) {
    float u[4], v[4];
    emb2(a[0], a[1], u); emb2(a[2], a[3], v);
    float psi[16];
#pragma unroll
    for (int i = 0; i < 4; i++)
#pragma unroll
        for (int j = 0; j < 4; j++) psi[i * 4 + j] = u[i] * v[j];
    ull pj[8];
#pragma unroll
    for (int j = 0; j < 8; j++) pj[j] = pk2(psi[2 * j], psi[2 * j + 1]);
    float eacc0 = 0.f, eacc1 = 0.f;
#pragma unroll 4
    for (int k = 0; k < 16; k++) {
        const ulonglong2* row = (const ulonglong2*)(M + k * 16);
        const ulonglong2 m0 = row[0], m1 = row[1], m2 = row[2], m3 = row[3];
        ull a0c = fmul2(m0.x, pj[0]);
        ull a1c = fmul2(m0.y, pj[1]);
        a0c = ffma2(m1.x, pj[2], a0c);
        a1c = ffma2(m1.y, pj[3], a1c);
        a0c = ffma2(m2.x, pj[4], a0c);
        a1c = ffma2(m2.y, pj[5], a1c);
        a0c = ffma2(m3.x, pj[6], a0c);
        a1c = ffma2(m3.y, pj[7], a1c);
        const ull s = fadd2(a0c, a1c);
        float lo, hi; unpk2(s, lo, hi);
        if (k & 1) eacc1 = fmaf(psi[k], lo + hi, eacc1);
        else       eacc0 = fmaf(psi[k], lo + hi, eacc0);
    }
    return eacc0 + eacc1;
}

// ---------------------------------------------------------------------------
// Main kernel: block = 32-element tile, warp w = circuit w of each stage,
// lane = element. All W/M reads are full-warp broadcasts. (R7 skeleton + PDL)
// ---------------------------------------------------------------------------
__global__ __launch_bounds__(TPB, 7)
void vqc_warp(const float* __restrict__ x, float* __restrict__ out, int B) {
    __shared__ __align__(16) ull   sW[12 * 256];   // 24 KB
    __shared__ __align__(16) float sM[5 * 256];    // 5 KB
    __shared__ float sH[32][17];                   // 2.1 KB, stride-17 pad

    const int tid = threadIdx.x;

    // x tile load first — overlaps with the (PDL) primary kernel still running.
    const int e0 = blockIdx.x * 32;                 // tile base element
    for (int i = tid; i < 32 * 13; i += TPB) {
        const long gi = (long)e0 * 13 + i;
        if (gi < (long)B * 13) {
            const int e = i / 13, j = i - 13 * e;
            sH[e][j] = x[gi];
        }
    }

    // Wait for build_WM's global writes, then stage W/M into smem.
    asm volatile("griddepcontrol.wait;" ::: "memory");
    {
        const float4* s1 = (const float4*)g_W12;
        float4* d1 = (float4*)sW;
        for (int i = tid; i < 12 * 128; i += TPB) d1[i] = s1[i];
        const float4* s2 = (const float4*)g_M;
        float4* d2 = (float4*)sM;
        for (int i = tid; i < 5 * 64; i += TPB) d2[i] = s2[i];
    }
    __syncthreads();

    const int w = tid >> 5;   // warp = circuit index within stage
    const int e = tid & 31;   // lane  = element within tile
    float a[4], o[4];

    // Stage A angles: H = [0, x0..x12, 0, 0]; circuit w uses H[4w..4w+3]
#pragma unroll
    for (int i = 0; i < 4; i++) {
        const int j = 4 * w + i;
        a[i] = (j >= 1 && j <= 13) ? sH[e][j - 1] : 0.f;
    }
    __syncthreads();

    // Stage A — warp-uniform specialization (no divergence: w is per-warp const)
    if (w == 0)      run4_half  (sW + 0 * 256, a[1], a[2], a[3], o);
    else if (w == 3) run4_sparse(sW + 3 * 256, a[0], a[1], o);
    else             run4       (sW + w * 256, a, o);
#pragma unroll
    for (int i = 0; i < 4; i++) sH[e][4 * w + i] = o[i];
    __syncthreads();
#pragma unroll
    for (int i = 0; i < 4; i++) a[i] = sH[e][4 * i + w];    // transposed wiring
    __syncthreads();

    // Stage B
    run4(sW + (4 + w) * 256, a, o);
#pragma unroll
    for (int i = 0; i < 4; i++) sH[e][4 * w + i] = o[i];
    __syncthreads();
#pragma unroll
    for (int i = 0; i < 4; i++) a[i] = sH[e][4 * i + w];
    __syncthreads();

    // Stage C
    run4(sW + (8 + w) * 256, a, o);
#pragma unroll
    for (int i = 0; i < 4; i++) sH[e][4 * w + i] = o[i];
    __syncthreads();
#pragma unroll
    for (int i = 0; i < 4; i++) a[i] = sH[e][4 * i + w];
    __syncthreads();

    // Stage D: quadratic form w
    const float h4 = run1(sM + w * 256, a);
    sH[e][w] = h4;
    __syncthreads();

    // Stage E: warp 0 only (MULT baked into sM[4]); warp-uniform branch
    if (w != 0) return;
#pragma unroll
    for (int i = 0; i < 4; i++) a[i] = sH[e][i];
    const float r = run1(sM + 4 * 256, a);
    if (e0 + e < B) out[e0 + e] = r;
}

extern "C" void kernel_launch(void* const* d_in, const int* in_sizes, int n_in,
                              void* d_out, int out_size) {
    const float* x     = (const float*)d_in[0];
    const float* theta = (const float*)d_in[1];
    if (n_in >= 2 && in_sizes[0] < in_sizes[1]) {
        x     = (const float*)d_in[1];
        theta = (const float*)d_in[0];
    }
    float* out = (float*)d_out;
    const int B = out_size;

    build_WM<<<17, 16>>>(theta);

    // Secondary launch with programmatic dependent launch (overlaps with build).
    cudaLaunchConfig_t cfg = {};
    cfg.gridDim  = dim3((B + 31) / 32);
    cfg.blockDim = dim3(TPB);
    cfg.dynamicSmemBytes = 0;
    cfg.stream = 0;
    cudaLaunchAttribute attrs[1];
    attrs[0].id = cudaLaunchAttributeProgrammaticStreamSerialization;
    attrs[0].val.programmaticStreamSerializationAllowed = 1;
    cfg.attrs = attrs;
    cfg.numAttrs = 1;
    cudaLaunchKernelEx(&cfg, vqc_warp, x, out, B);
}

// round 14
// speedup vs baseline: 1.4094x; 1.2538x over previous
#include <cuda_runtime.h>

#define TPB 128
typedef unsigned long long ull;

// MULT = pi - float-eps, folded into the stage-E form.
#define MULT_F (3.141592653589793 - 1.1920928955078125e-07)

// Precomputed bilinear-form tensor, packed f32x2, contiguous:
//   [c*200 + a*10 + b]        : circuits 0..11 (stages A,B,C), (N_q0, N_q1)
//   [c*200 + 100 + a*10 + b]  : circuits 0..11, (N_q2, N_q3)
//   [2400 + d*100 + a*10 + b] : stage-D circuits d=0..3, (N, N) duplicated
//   [2800 + a*10 + b]         : stage-E form, (N*MULT, N*MULT)
__device__ __align__(16) ull g_N[2900];

// theta slice per circuit: A->theta[0], B->theta[3], C->theta[4], D->theta[1], E->theta[2][0]
__device__ __forceinline__ int circ_slice(int c) {
    if (c < 4)  return c;
    if (c < 8)  return 12 + (c - 4);
    if (c < 12) return 16 + (c - 8);
    if (c < 16) return 4 + (c - 12);
    return 8;
}

__device__ __forceinline__ ull pk2(float lo, float hi) {
    ull r; asm("mov.b64 %0, {%1, %2};" : "=l"(r) : "f"(lo), "f"(hi)); return r;
}
__device__ __forceinline__ void unpk2(ull v, float& lo, float& hi) {
    asm("mov.b64 {%0, %1}, %2;" : "=f"(lo), "=f"(hi) : "l"(v));
}
__device__ __forceinline__ ull ffma2(ull a, ull b, ull c) {
    ull d; asm("fma.rn.f32x2 %0, %1, %2, %3;" : "=l"(d) : "l"(a), "l"(b), "l"(c)); return d;
}
__device__ __forceinline__ ull fmul2(ull a, ull b) {
    ull d; asm("mul.rn.f32x2 %0, %1, %2;" : "=l"(d) : "l"(a), "l"(b)); return d;
}
__device__ __forceinline__ ull fadd2(ull a, ull b) {
    ull d; asm("add.rn.f32x2 %0, %1, %2;" : "=l"(d) : "l"(a), "l"(b)); return d;
}

// ---------------------------------------------------------------------------
// Build kernel: one block per circuit (grid 17, block 100).
// Threads 0..15 build the 16x16 unitary columns; then 100 threads compute the
// symmetrized bilinear tensor N[a][b] (a,b index unordered pairs, i<=i').
// ---------------------------------------------------------------------------
__global__ void build_WM(const float* __restrict__ theta) {
    const int c = blockIdx.x, t = threadIdx.x;
    __shared__ float sWr[16][16], sWi[16][16];   // [k][col]

    if (t < 16) {
        const int col = t;
        const float* w = theta + circ_slice(c) * 48;
        float sr[16], si[16];
#pragma unroll
        for (int i = 0; i < 16; i++) { sr[i] = (i == col) ? 1.f : 0.f; si[i] = 0.f; }
#pragma unroll
        for (int l = 0; l < 4; l++) {
#pragma unroll
            for (int q = 0; q < 4; q++) {
                const float phi = w[(l * 4 + q) * 3 + 0];
                const float th  = w[(l * 4 + q) * 3 + 1];
                const float om  = w[(l * 4 + q) * 3 + 2];
                float ch, sh, ca, sa, cb, sb;
                __sincosf(0.5f * th, &sh, &ch);
                __sincosf(0.5f * (phi + om), &sa, &ca);
                __sincosf(0.5f * (phi - om), &sb, &cb);
                const float u00r =  ca * ch, u00i = -sa * ch;
                const float u01r = -cb * sh, u01i = -sb * sh;
                const float u10r =  cb * sh, u10i = -sb * sh;
                const float u11r =  ca * ch, u11i =  sa * ch;
                const int mask = 8 >> q;
#pragma unroll
                for (int k = 0; k < 16; k++) {
                    if (k & mask) continue;
                    const int k1 = k | mask;
                    float ar = sr[k],  ai = si[k];
                    float br = sr[k1], bi = si[k1];
                    sr[k]  = u00r * ar - u00i * ai + u01r * br - u01i * bi;
                    si[k]  = u00r * ai + u00i * ar + u01r * bi + u01i * br;
                    sr[k1] = u10r * ar - u10i * ai + u11r * br - u11i * bi;
                    si[k1] = u10r * ai + u10i * ar + u11r * bi + u11i * br;
                }
            }
            const int r = (l % 3) + 1;
#pragma unroll
            for (int q = 0; q < 4; q++) {
                const int cm = 8 >> q;
                const int tm = 8 >> ((q + r) & 3);
#pragma unroll
                for (int k = 0; k < 16; k++) {
                    if ((k & cm) && !(k & tm)) {
                        const int k1 = k | tm;
                        float tr = sr[k], ti = si[k];
                        sr[k] = sr[k1]; si[k] = si[k1];
                        sr[k1] = tr;    si[k1] = ti;
                    }
                }
            }
        }
#pragma unroll
        for (int k = 0; k < 16; k++) { sWr[k][col] = sr[k]; sWi[k][col] = si[k]; }
    }
    __syncthreads();

    // N tensor: thread t -> (a, b). Sum over index orderings and k.
    const int PI[10] = {0,0,0,0,1,1,1,2,2,3};
    const int PJ[10] = {0,1,2,3,1,2,3,2,3,3};
    const int a = t / 10, b = t % 10;   // t < 100
    const int i0 = PI[a], i1 = PJ[a], j0 = PI[b], j1 = PJ[b];
    const int na = (i0 == i1) ? 1 : 2;
    const int nb = (j0 == j1) ? 1 : 2;

    float n0 = 0.f, n1 = 0.f, n2 = 0.f, n3 = 0.f;
    for (int ai = 0; ai < na; ai++) {
        const int A0 = ai ? i1 : i0, A1 = ai ? i0 : i1;
        for (int bi = 0; bi < nb; bi++) {
            const int B0 = bi ? j1 : j0, B1 = bi ? j0 : j1;
            const int r  = 4 * A0 + B0;
            const int cc = 4 * A1 + B1;
#pragma unroll
            for (int k = 0; k < 16; k++) {
                const float tt = sWr[k][r] * sWr[k][cc] + sWi[k][r] * sWi[k][cc];
                n0 += (k & 8) ? -tt : tt;
                n1 += (k & 4) ? -tt : tt;
                n2 += (k & 2) ? -tt : tt;
                n3 += (k & 1) ? -tt : tt;
            }
        }
    }

    const int idx = a * 10 + b;
    if (c < 12) {
        g_N[c * 200 + idx]       = pk2(n0, n1);
        g_N[c * 200 + 100 + idx] = pk2(n2, n3);
    } else if (c < 16) {
        g_N[2400 + (c - 12) * 100 + idx] = pk2(n0, n0);
    } else {
        const float ns = n0 * (float)MULT_F;
        g_N[2800 + idx] = pk2(ns, ns);
    }
    // PDL: allow the dependent (main) kernel to start scheduling.
    asm volatile("griddepcontrol.launch_dependents;" ::: "memory");
}

// ---------------------------------------------------------------------------
// Per-circuit evaluation via bilinear forms.
// ---------------------------------------------------------------------------
__device__ __forceinline__ void make_pq(const float* a, ull* pAp, ull* qBp) {
    float s0, c0, s1, c1, s2, c2, s3, c3;
    __sincosf(0.5f * a[0], &s0, &c0);
    __sincosf(0.5f * a[1], &s1, &c1);
    __sincosf(0.5f * a[2], &s2, &c2);
    __sincosf(0.5f * a[3], &s3, &c3);
    const float u0 = c0 * c1, u1 = c0 * s1, u2 = s0 * c1, u3 = s0 * s1;
    const float v0 = c2 * c3, v1 = c2 * s3, v2 = s2 * c3, v3 = s2 * s3;
    const float pA[10] = { u0*u0, u0*u1, u0*u2, u0*u3, u1*u1,
                           u1*u2, u1*u3, u2*u2, u2*u3, u3*u3 };
    const float qB[10] = { v0*v0, v0*v1, v0*v2, v0*v3, v1*v1,
                           v1*v2, v1*v3, v2*v2, v2*v3, v3*v3 };
#pragma unroll
    for (int i = 0; i < 10; i++) { pAp[i] = pk2(pA[i], pA[i]); qBp[i] = pk2(qB[i], qB[i]); }
}

// 4 expvals: forms (q0,q1) at N[0..99], (q2,q3) at N[100..199], packed.
__device__ __forceinline__ void runQ4(const ull* __restrict__ N, const float* a, float* o) {
    ull pAp[10], qBp[10];
    make_pq(a, pAp, qBp);
    ull e01 = 0ull, e23 = 0ull;
#pragma unroll
    for (int t = 0; t < 10; t++) {
        const ulonglong2* r01 = (const ulonglong2*)(N + t * 10);
        const ulonglong2* r23 = (const ulonglong2*)(N + 100 + t * 10);
        ull t0 = fmul2(r01[0].x, qBp[0]), t1 = fmul2(r01[0].y, qBp[1]);
        t0 = ffma2(r01[1].x, qBp[2], t0); t1 = ffma2(r01[1].y, qBp[3], t1);
        t0 = ffma2(r01[2].x, qBp[4], t0); t1 = ffma2(r01[2].y, qBp[5], t1);
        t0 = ffma2(r01[3].x, qBp[6], t0); t1 = ffma2(r01[3].y, qBp[7], t1);
        t0 = ffma2(r01[4].x, qBp[8], t0); t1 = ffma2(r01[4].y, qBp[9], t1);
        e01 = ffma2(pAp[t], fadd2(t0, t1), e01);
        ull s0 = fmul2(r23[0].x, qBp[0]), s1 = fmul2(r23[0].y, qBp[1]);
        s0 = ffma2(r23[1].x, qBp[2], s0); s1 = ffma2(r23[1].y, qBp[3], s1);
        s0 = ffma2(r23[2].x, qBp[4], s0); s1 = ffma2(r23[2].y, qBp[5], s1);
        s0 = ffma2(r23[3].x, qBp[6], s0); s1 = ffma2(r23[3].y, qBp[7], s1);
        s0 = ffma2(r23[4].x, qBp[8], s0); s1 = ffma2(r23[4].y, qBp[9], s1);
        e23 = ffma2(pAp[t], fadd2(s0, s1), e23);
    }
    float lo, hi;
    unpk2(e01, lo, hi); o[0] = lo; o[1] = hi;
    unpk2(e23, lo, hi); o[2] = lo; o[3] = hi;
}

// Single expval (duplicated-packed form at N[0..99]).
__device__ __forceinline__ float runQ1(const ull* __restrict__ N, const float* a) {
    ull pAp[10], qBp[10];
    make_pq(a, pAp, qBp);
    ull e = 0ull;
#pragma unroll
    for (int t = 0; t < 10; t++) {
        const ulonglong2* r = (const ulonglong2*)(N + t * 10);
        ull t0 = fmul2(r[0].x, qBp[0]), t1 = fmul2(r[0].y, qBp[1]);
        t0 = ffma2(r[1].x, qBp[2], t0); t1 = ffma2(r[1].y, qBp[3], t1);
        t0 = ffma2(r[2].x, qBp[4], t0); t1 = ffma2(r[2].y, qBp[5], t1);
        t0 = ffma2(r[3].x, qBp[6], t0); t1 = ffma2(r[3].y, qBp[7], t1);
        t0 = ffma2(r[4].x, qBp[8], t0); t1 = ffma2(r[4].y, qBp[9], t1);
        e = ffma2(pAp[t], fadd2(t0, t1), e);
    }
    float lo, hi; unpk2(e, lo, hi);
    return lo;
}

// ---------------------------------------------------------------------------
// Main kernel: block = 32-element tile, warp w = circuit w of each stage,
// lane = element. All N reads are full-warp broadcasts. (R7 skeleton + PDL)
// ---------------------------------------------------------------------------
__global__ __launch_bounds__(TPB, 7)
void vqc_warp(const float* __restrict__ x, float* __restrict__ out, int B) {
    __shared__ __align__(16) ull sN[2900];     // 23.2 KB
    __shared__ float sH[32][17];               // 2.1 KB, stride-17 pad

    const int tid = threadIdx.x;

    // x tile load first — overlaps with the (PDL) primary kernel still running.
    const int e0 = blockIdx.x * 32;
    for (int i = tid; i < 32 * 13; i += TPB) {
        const long gi = (long)e0 * 13 + i;
        if (gi < (long)B * 13) sH[i / 13][i % 13] = x[gi];
    }

    asm volatile("griddepcontrol.wait;" ::: "memory");
    {
        const float4* s1 = (const float4*)g_N;
        float4* d1 = (float4*)sN;
        for (int i = tid; i < 1450; i += TPB) d1[i] = s1[i];
    }
    __syncthreads();

    const int w = tid >> 5;   // warp = circuit index within stage
    const int e = tid & 31;   // lane  = element within tile
    float a[4], o[4];

    // Stage A angles: H = [0, x0..x12, 0, 0]; circuit w uses H[4w..4w+3]
#pragma unroll
    for (int i = 0; i < 4; i++) {
        const int j = 4 * w + i;
        a[i] = (j >= 1 && j <= 13) ? sH[e][j - 1] : 0.f;
    }
    __syncthreads();

    // Stage A
    runQ4(sN + w * 200, a, o);
#pragma unroll
    for (int i = 0; i < 4; i++) sH[e][4 * w + i] = o[i];
    __syncthreads();
#pragma unroll
    for (int i = 0; i < 4; i++) a[i] = sH[e][4 * i + w];    // transposed wiring
    __syncthreads();

    // Stage B
    runQ4(sN + (4 + w) * 200, a, o);
#pragma unroll
    for (int i = 0; i < 4; i++) sH[e][4 * w + i] = o[i];
    __syncthreads();
#pragma unroll
    for (int i = 0; i < 4; i++) a[i] = sH[e][4 * i + w];
    __syncthreads();

    // Stage C
    runQ4(sN + (8 + w) * 200, a, o);
#pragma unroll
    for (int i = 0; i < 4; i++) sH[e][4 * w + i] = o[i];
    __syncthreads();
#pragma unroll
    for (int i = 0; i < 4; i++) a[i] = sH[e][4 * i + w];
    __syncthreads();

    // Stage D: form w
    const float h4 = runQ1(sN + 2400 + w * 100, a);
    sH[e][w] = h4;
    __syncthreads();

    // Stage E: warp 0 only (MULT baked into the E form); warp-uniform branch
    if (w != 0) return;
#pragma unroll
    for (int i = 0; i < 4; i++) a[i] = sH[e][i];
    const float r = runQ1(sN + 2800, a);
    if (e0 + e < B) out[e0 + e] = r;
}

extern "C" void kernel_launch(void* const* d_in, const int* in_sizes, int n_in,
                              void* d_out, int out_size) {
    const float* x     = (const float*)d_in[0];
    const float* theta = (const float*)d_in[1];
    if (n_in >= 2 && in_sizes[0] < in_sizes[1]) {
        x     = (const float*)d_in[1];
        theta = (const float*)d_in[0];
    }
    float* out = (float*)d_out;
    const int B = out_size;

    build_WM<<<17, 100>>>(theta);

    // Secondary launch with programmatic dependent launch (overlaps with build).
    cudaLaunchConfig_t cfg = {};
    cfg.gridDim  = dim3((B + 31) / 32);
    cfg.blockDim = dim3(TPB);
    cfg.dynamicSmemBytes = 0;
    cfg.stream = 0;
    cudaLaunchAttribute attrs[1];
    attrs[0].id = cudaLaunchAttributeProgrammaticStreamSerialization;
    attrs[0].val.programmaticStreamSerializationAllowed = 1;
    cfg.attrs = attrs;
    cfg.numAttrs = 1;
    cudaLaunchKernelEx(&cfg, vqc_warp, x, out, B);
}